// round 7
// baseline (speedup 1.0000x reference)
#include <cuda_runtime.h>
#include <math.h>
#include <stdint.h>

#define W_ 192
#define H_ 192
#define D_ 160
#define HW_ (H_ * W_)
#define CHUNK 80
#define NPLANES 84
#define NPAIRS  42
#define NBLOCKS (6 * 12 * 4)

#define NTHREADS 384
#define NPROD    128

#define BAR_FULL0  1
#define BAR_FULL1  2
#define BAR_EMPTY0 3
#define BAR_EMPTY1 4
#define BAR_PROD   5

__device__ double   g_acc;
__device__ unsigned g_cnt;

static __device__ __forceinline__ void bar_sync_n(int id, int cnt) {
    asm volatile("bar.sync %0, %1;" :: "r"(id), "r"(cnt) : "memory");
}
static __device__ __forceinline__ void bar_arrive_n(int id, int cnt) {
    asm volatile("bar.arrive %0, %1;" :: "r"(id), "r"(cnt) : "memory");
}
static __device__ __forceinline__ void cp_async8(uint32_t dst, const float* src,
                                                 unsigned srcsz) {
    asm volatile("cp.async.ca.shared.global [%0], [%1], 8, %2;"
                 :: "r"(dst), "l"(src), "r"(srcsz) : "memory");
}
static __device__ __forceinline__ void cp_commit() {
    asm volatile("cp.async.commit_group;" ::: "memory");
}
static __device__ __forceinline__ void cp_wait2() {
    asm volatile("cp.async.wait_group 2;" ::: "memory");
}

__global__ void __launch_bounds__(NTHREADS, 2)
lncc_k(const float* __restrict__ src, const float* __restrict__ tgt,
       float* __restrict__ out)
{
    // tile: 3 pair-buffers x 2 planes x [img][haloRow(20)][col(36 pad 40)]
    __shared__ float tile[3][2][2][20][40];
    // rs: 2 buffers x 2 planes x [ch][haloRow(20)][x(32)]
    __shared__ float rs[2][2][5][20][32];
    __shared__ float wsum[12];

    const int tid = threadIdx.x;
    const int x0  = blockIdx.x * 32;
    const int y0  = blockIdx.y * 16;
    const int b   = blockIdx.z >> 1;
    const int z0  = (blockIdx.z & 1) * CHUNK;
    const int zstart = z0 - 2;

    const float* baseS = src + (size_t)b * (D_ * HW_);
    const float* baseT = tgt + (size_t)b * (D_ * HW_);

    float acc = 0.f;

    if (tid < NPROD) {
        // ============================ PRODUCER (128) ============================
        // Halo plane: 36 cols x 20 rows x 2 imgs = 720 8B pairs (18 pairs/row).
        // Slot sl covers pair index i = tid + 128*sl, sl = 0..5.
        uint32_t soffb[6];
        const float* gbase[6];
        unsigned vmask = 0;   // bit sl: slot used AND xy-valid
        unsigned umask = 0;   // bit sl: slot used
        #pragma unroll
        for (int sl = 0; sl < 6; sl++) {
            soffb[sl] = 0; gbase[sl] = baseS;
            const int i = tid + NPROD * sl;
            if (i < 720) {
                umask |= 1u << sl;
                const int img = (i >= 360) ? 1 : 0;
                const int j   = i - img * 360;
                const int row = j / 18;
                const int pc  = j - row * 18;
                soffb[sl] = (uint32_t)(img * 800 + row * 40 + pc * 2) * 4u;
                const int gy = y0 + row - 2;
                const int gx = x0 + pc * 2 - 2;   // even; pairs never straddle W
                const bool v = ((unsigned)gy < (unsigned)H_) &&
                               ((unsigned)gx < (unsigned)W_);
                if (v) vmask |= 1u << sl;
                gbase[sl] = (img ? baseT : baseS) + (v ? (gy * W_ + gx) : 0);
            }
        }

        const uint32_t sbase =
            (uint32_t)__cvta_generic_to_shared(&tile[0][0][0][0][0]);

        auto issue_pair = [&](int m) {          // planes 2m, 2m+1 -> pairbuf m%3
            const uint32_t pb = sbase + (uint32_t)(m % 3) * 12800u;
            #pragma unroll
            for (int pl = 0; pl < 2; pl++) {
                const int zp   = zstart + 2 * m + pl;
                const bool zin = (unsigned)zp < (unsigned)D_;
                const int zoff = zin ? zp * HW_ : 0;
                const uint32_t tb = pb + (uint32_t)pl * 6400u;
                #pragma unroll
                for (int sl = 0; sl < 6; sl++) {
                    if (umask & (1u << sl)) {
                        unsigned sz = (zin && (vmask & (1u << sl))) ? 8u : 0u;
                        cp_async8(tb + soffb[sl], gbase[sl] + zoff, sz);
                    }
                }
            }
            cp_commit();
        };

        // x-phase for one item (r, x4): tile plane tb -> rs plane rsq
        auto xitem = [&](const float* tb, float* rsq, int item) {
            const int r  = item >> 3;
            const int x4 = (item & 7) << 2;
            const float* rowS = tb + r * 40 + x4;
            const float* rowT = rowS + 800;
            float4 a0 = *(const float4*)(rowS);
            float4 a1 = *(const float4*)(rowS + 4);
            float4 b0 = *(const float4*)(rowT);
            float4 b1 = *(const float4*)(rowT + 4);
            float sc[8] = {a0.x,a0.y,a0.z,a0.w,a1.x,a1.y,a1.z,a1.w};
            float tc[8] = {b0.x,b0.y,b0.z,b0.w,b1.x,b1.y,b1.z,b1.w};
            const int ro = r * 32 + x4;
            {
                float S0=0.f, T0=0.f;
                #pragma unroll
                for (int j = 0; j < 5; j++) { S0 += sc[j]; T0 += tc[j]; }
                float Sv[4], Tv[4];
                Sv[0]=S0; Tv[0]=T0;
                #pragma unroll
                for (int w = 1; w < 4; w++) {
                    Sv[w] = Sv[w-1] - sc[w-1] + sc[w+4];
                    Tv[w] = Tv[w-1] - tc[w-1] + tc[w+4];
                }
                *(float4*)(rsq + 0*640 + ro) = make_float4(Sv[0],Sv[1],Sv[2],Sv[3]);
                *(float4*)(rsq + 1*640 + ro) = make_float4(Tv[0],Tv[1],Tv[2],Tv[3]);
            }
            {
                float SS0=0.f, TT0=0.f;
                #pragma unroll
                for (int j = 0; j < 5; j++) {
                    SS0 = fmaf(sc[j], sc[j], SS0);
                    TT0 = fmaf(tc[j], tc[j], TT0);
                }
                float SSv[4], TTv[4];
                SSv[0]=SS0; TTv[0]=TT0;
                #pragma unroll
                for (int w = 1; w < 4; w++) {
                    SSv[w] = SSv[w-1] - sc[w-1]*sc[w-1] + sc[w+4]*sc[w+4];
                    TTv[w] = TTv[w-1] - tc[w-1]*tc[w-1] + tc[w+4]*tc[w+4];
                }
                *(float4*)(rsq + 2*640 + ro) = make_float4(SSv[0],SSv[1],SSv[2],SSv[3]);
                *(float4*)(rsq + 3*640 + ro) = make_float4(TTv[0],TTv[1],TTv[2],TTv[3]);
            }
            {
                float ST0=0.f;
                #pragma unroll
                for (int j = 0; j < 5; j++) ST0 = fmaf(sc[j], tc[j], ST0);
                float STv[4];
                STv[0]=ST0;
                #pragma unroll
                for (int w = 1; w < 4; w++)
                    STv[w] = STv[w-1] - sc[w-1]*tc[w-1] + sc[w+4]*tc[w+4];
                *(float4*)(rsq + 4*640 + ro) = make_float4(STv[0],STv[1],STv[2],STv[3]);
            }
        };

        issue_pair(0);
        issue_pair(1);

        for (int k = 0; k < NPAIRS; k++) {
            const int q = k & 1;
            // consumers done with rs[q] (pair k-2); block-wide -> also fences
            // producers past x-phase of pair k-1, so tile[(k+2)%3] is reusable.
            bar_sync_n(BAR_EMPTY0 + q, NTHREADS);
            issue_pair(k + 2);
            cp_wait2();                         // pair k's group has landed
            bar_sync_n(BAR_PROD, NPROD);        // cross-thread visibility

            {
                const float* pb = &tile[k % 3][0][0][0][0];
                float* rq = &rs[q][0][0][0][0];
                xitem(pb,        rq,        tid);          // plane 2k
                xitem(pb + 1600, rq + 3200, tid);          // plane 2k+1
                if (tid < 32) {
                    xitem(pb,        rq,        128 + tid);
                    xitem(pb + 1600, rq + 3200, 128 + tid);
                }
            }
            bar_arrive_n(BAR_FULL0 + q, NTHREADS);  // rs[q] published (pair k)
        }
    } else {
        // ============================ CONSUMER (256) ============================
        const int ctid = tid - NPROD;
        const int ctx  = ctid & 31;
        const int cty  = ctid >> 5;             // 0..7
        const int yb   = 2 * cty;

        float ring[5][2][5];
        float run[2][5];
        #pragma unroll
        for (int s = 0; s < 5; s++)
            #pragma unroll
            for (int pp = 0; pp < 2; pp++)
                #pragma unroll
                for (int c = 0; c < 5; c++) ring[s][pp][c] = 0.f;
        #pragma unroll
        for (int pp = 0; pp < 2; pp++)
            #pragma unroll
            for (int c = 0; c < 5; c++) run[pp][c] = 0.f;

        bar_arrive_n(BAR_EMPTY0, NTHREADS);
        bar_arrive_n(BAR_EMPTY1, NTHREADS);

        // one plane's worth of consumer work; s = ring slot (compile-time)
        auto consume_plane = [&](const float* rp, int s, bool live) {
            #pragma unroll
            for (int c = 0; c < 5; c++) {
                const float* col = rp + c * 640 + yb * 32 + ctx;
                float v0 = col[0*32];
                float v1 = col[1*32];
                float v2 = col[2*32];
                float v3 = col[3*32];
                float v4 = col[4*32];
                float v5 = col[5*32];
                float n0 = ((v0 + v1) + (v2 + v3)) + v4;
                float n1 = n0 - v0 + v5;
                run[0][c]    += n0 - ring[s][0][c];
                ring[s][0][c] = n0;
                run[1][c]    += n1 - ring[s][1][c];
                ring[s][1][c] = n1;
            }
            if (live) {
                const float inv = 1.f / 125.f;
                #pragma unroll
                for (int pp = 0; pp < 2; pp++) {
                    float sm = run[pp][0] * inv;
                    float tm = run[pp][1] * inv;
                    float sv = fmaf(-sm, sm, run[pp][2] * inv);
                    float tv = fmaf(-tm, tm, run[pp][3] * inv);
                    float cr = fmaf(-sm, tm, run[pp][4] * inv);
                    float den = fmaf(sv, tv, 1e-5f);
                    acc += __fdividef(cr * cr, den);
                }
            }
        };

        for (int kb = 0; kb < 45; kb += 5) {
            #pragma unroll
            for (int jj = 0; jj < 5; jj++) {     // compile-time slot pattern
                const int k = kb + jj;
                if (k >= NPAIRS) break;          // 42 = 8*5 + 2
                const int q  = k & 1;
                const int s0 = (2 * jj) % 5;
                const int s1 = (2 * jj + 1) % 5;
                bar_sync_n(BAR_FULL0 + q, NTHREADS);

                const float* rq = &rs[q][0][0][0][0];
                consume_plane(rq,        s0, k >= 2);   // plane 2k
                consume_plane(rq + 3200, s1, k >= 2);   // plane 2k+1

                bar_arrive_n(BAR_EMPTY0 + q, NTHREADS);
            }
        }
    }

    // ---- block reduction over all 384 threads (producers contribute 0) ----
    __syncthreads();
    #pragma unroll
    for (int o = 16; o > 0; o >>= 1)
        acc += __shfl_xor_sync(0xffffffffu, acc, o);
    if ((tid & 31) == 0) wsum[tid >> 5] = acc;
    __syncthreads();

    if (tid == 0) {
        float bsum = 0.f;
        #pragma unroll
        for (int i = 0; i < 12; i++) bsum += wsum[i];
        atomicAdd(&g_acc, (double)bsum);
        __threadfence();
        unsigned done = atomicAdd(&g_cnt, 1u);
        if (done == NBLOCKS - 1) {
            double total = atomicAdd(&g_acc, 0.0);  // fenced read
            const double n = 2.0 * 160.0 * 192.0 * 192.0;
            float loss = (float)(1.0 - total / n);
            if (isnan(loss) || isinf(loss)) loss = 1.0f;
            out[0] = loss;
            *((volatile double*)&g_acc)   = 0.0;
            *((volatile unsigned*)&g_cnt) = 0u;
        }
    }
}

extern "C" void kernel_launch(void* const* d_in, const int* in_sizes, int n_in,
                              void* d_out, int out_size)
{
    (void)in_sizes; (void)n_in; (void)out_size;
    const float* src = (const float*)d_in[0];
    const float* tgt = (const float*)d_in[1];

    lncc_k<<<dim3(6, 12, 4), NTHREADS>>>(src, tgt, (float*)d_out);
}

// round 8
// speedup vs baseline: 1.3155x; 1.3155x over previous
#include <cuda_runtime.h>
#include <math.h>
#include <stdint.h>

#define W_ 192
#define H_ 192
#define D_ 160
#define HW_ (H_ * W_)
#define CHUNK 80
#define NPAIRS  42
#define NBLOCKS (6 * 24 * 4)

#define NTHREADS 256
#define NPROD    128

#define BAR_FULL0  1
#define BAR_FULL1  2
#define BAR_EMPTY0 3
#define BAR_EMPTY1 4
#define BAR_PROD   5

// tile geometry: 32 x 8 outputs, halo 36 x 12
#define HROWS 12
#define TROWF 480              /* floats per img plane: 12*40 */
#define TPLANEF 960            /* floats per plane (2 imgs) */
#define TPAIRF 1920            /* floats per pair buffer */
#define RSCHF 384              /* rs channel stride: 12*32 */
#define RSPLANEF 1920          /* rs plane stride: 5*384 */
#define NXITEM 96              /* 12 rows * 8 groups */
#define NPAIRS_LD 432          /* 12*18*2 8B pairs per plane */

__device__ double   g_acc;
__device__ unsigned g_cnt;

static __device__ __forceinline__ void bar_sync_n(int id, int cnt) {
    asm volatile("bar.sync %0, %1;" :: "r"(id), "r"(cnt) : "memory");
}
static __device__ __forceinline__ void bar_arrive_n(int id, int cnt) {
    asm volatile("bar.arrive %0, %1;" :: "r"(id), "r"(cnt) : "memory");
}
static __device__ __forceinline__ void cp_async8(uint32_t dst, const float* src,
                                                 unsigned srcsz) {
    asm volatile("cp.async.ca.shared.global [%0], [%1], 8, %2;"
                 :: "r"(dst), "l"(src), "r"(srcsz) : "memory");
}
static __device__ __forceinline__ void cp_commit() {
    asm volatile("cp.async.commit_group;" ::: "memory");
}
static __device__ __forceinline__ void cp_wait2() {
    asm volatile("cp.async.wait_group 2;" ::: "memory");
}

__global__ void __launch_bounds__(NTHREADS, 2)
lncc_k(const float* __restrict__ src, const float* __restrict__ tgt,
       float* __restrict__ out)
{
    // tile: 3 pair-buffers x 2 planes x [img][haloRow(12)][col(36 pad 40)]
    __shared__ float tile[3][2][2][HROWS][40];
    // rs: 2 buffers x 2 planes x [ch(5)][haloRow(12)][x(32)]
    __shared__ float rs[2][2][5][HROWS][32];
    __shared__ float wsum[8];

    const int tid = threadIdx.x;
    const int x0  = blockIdx.x * 32;
    const int y0  = blockIdx.y * 8;
    const int b   = blockIdx.z >> 1;
    const int z0  = (blockIdx.z & 1) * CHUNK;
    const int zstart = z0 - 2;

    const float* baseS = src + (size_t)b * (D_ * HW_);
    const float* baseT = tgt + (size_t)b * (D_ * HW_);

    float acc = 0.f;

    if (tid < NPROD) {
        // ========================= PRODUCER (128) =========================
        // Halo plane: 36 cols x 12 rows x 2 imgs = 432 8B pairs (18/row).
        // Slot sl covers pair index i = tid + 128*sl, sl = 0..3.
        uint32_t soffb[4];
        const float* gbase[4];
        unsigned vmask = 0;   // bit sl: used AND xy-valid
        unsigned umask = 0;   // bit sl: used
        #pragma unroll
        for (int sl = 0; sl < 4; sl++) {
            soffb[sl] = 0; gbase[sl] = baseS;
            const int i = tid + NPROD * sl;
            if (i < NPAIRS_LD) {
                umask |= 1u << sl;
                const int img = (i >= 216) ? 1 : 0;
                const int j   = i - img * 216;
                const int row = j / 18;
                const int pc  = j - row * 18;
                soffb[sl] = (uint32_t)(img * TROWF + row * 40 + pc * 2) * 4u;
                const int gy = y0 + row - 2;
                const int gx = x0 + pc * 2 - 2;  // even; pairs never straddle W
                const bool v = ((unsigned)gy < (unsigned)H_) &&
                               ((unsigned)gx < (unsigned)W_);
                if (v) vmask |= 1u << sl;
                gbase[sl] = (img ? baseT : baseS) + (v ? (gy * W_ + gx) : 0);
            }
        }

        const uint32_t sbase =
            (uint32_t)__cvta_generic_to_shared(&tile[0][0][0][0][0]);

        auto issue_pair = [&](int m) {          // planes 2m,2m+1 -> pairbuf m%3
            const uint32_t pb = sbase + (uint32_t)(m % 3) * (TPAIRF * 4u);
            #pragma unroll
            for (int pl = 0; pl < 2; pl++) {
                const int zp   = zstart + 2 * m + pl;
                const bool zin = (unsigned)zp < (unsigned)D_;
                const int zoff = zin ? zp * HW_ : 0;
                const uint32_t tb = pb + (uint32_t)pl * (TPLANEF * 4u);
                #pragma unroll
                for (int sl = 0; sl < 4; sl++) {
                    if (umask & (1u << sl)) {
                        unsigned sz = (zin && (vmask & (1u << sl))) ? 8u : 0u;
                        cp_async8(tb + soffb[sl], gbase[sl] + zoff, sz);
                    }
                }
            }
            cp_commit();
        };

        // x-phase for one item (r, x4): tile plane tb -> rs plane rsq
        auto xitem = [&](const float* tb, float* rsq, int item) {
            const int r  = item >> 3;
            const int x4 = (item & 7) << 2;
            const float* rowS = tb + r * 40 + x4;
            const float* rowT = rowS + TROWF;
            float4 a0 = *(const float4*)(rowS);
            float4 a1 = *(const float4*)(rowS + 4);
            float4 b0 = *(const float4*)(rowT);
            float4 b1 = *(const float4*)(rowT + 4);
            float sc[8] = {a0.x,a0.y,a0.z,a0.w,a1.x,a1.y,a1.z,a1.w};
            float tc[8] = {b0.x,b0.y,b0.z,b0.w,b1.x,b1.y,b1.z,b1.w};
            const int ro = r * 32 + x4;
            {
                float S0=0.f, T0=0.f;
                #pragma unroll
                for (int j = 0; j < 5; j++) { S0 += sc[j]; T0 += tc[j]; }
                float Sv[4], Tv[4];
                Sv[0]=S0; Tv[0]=T0;
                #pragma unroll
                for (int w = 1; w < 4; w++) {
                    Sv[w] = Sv[w-1] - sc[w-1] + sc[w+4];
                    Tv[w] = Tv[w-1] - tc[w-1] + tc[w+4];
                }
                *(float4*)(rsq + 0*RSCHF + ro) = make_float4(Sv[0],Sv[1],Sv[2],Sv[3]);
                *(float4*)(rsq + 1*RSCHF + ro) = make_float4(Tv[0],Tv[1],Tv[2],Tv[3]);
            }
            {
                float SS0=0.f, TT0=0.f;
                #pragma unroll
                for (int j = 0; j < 5; j++) {
                    SS0 = fmaf(sc[j], sc[j], SS0);
                    TT0 = fmaf(tc[j], tc[j], TT0);
                }
                float SSv[4], TTv[4];
                SSv[0]=SS0; TTv[0]=TT0;
                #pragma unroll
                for (int w = 1; w < 4; w++) {
                    SSv[w] = SSv[w-1] - sc[w-1]*sc[w-1] + sc[w+4]*sc[w+4];
                    TTv[w] = TTv[w-1] - tc[w-1]*tc[w-1] + tc[w+4]*tc[w+4];
                }
                *(float4*)(rsq + 2*RSCHF + ro) = make_float4(SSv[0],SSv[1],SSv[2],SSv[3]);
                *(float4*)(rsq + 3*RSCHF + ro) = make_float4(TTv[0],TTv[1],TTv[2],TTv[3]);
            }
            {
                float ST0=0.f;
                #pragma unroll
                for (int j = 0; j < 5; j++) ST0 = fmaf(sc[j], tc[j], ST0);
                float STv[4];
                STv[0]=ST0;
                #pragma unroll
                for (int w = 1; w < 4; w++)
                    STv[w] = STv[w-1] - sc[w-1]*tc[w-1] + sc[w+4]*tc[w+4];
                *(float4*)(rsq + 4*RSCHF + ro) = make_float4(STv[0],STv[1],STv[2],STv[3]);
            }
        };

        issue_pair(0);
        issue_pair(1);

        for (int k = 0; k < NPAIRS; k++) {
            const int q = k & 1;
            // consumers done with rs[q] (pair k-2); block-wide -> also fences
            // producers past x-phase of pair k-1, so tile[(k+2)%3] is reusable.
            bar_sync_n(BAR_EMPTY0 + q, NTHREADS);
            issue_pair(k + 2);
            cp_wait2();                          // pair k's group has landed
            bar_sync_n(BAR_PROD, NPROD);         // cross-thread visibility

            if (tid < NXITEM) {
                const float* pb = &tile[k % 3][0][0][0][0];
                float* rq = &rs[q][0][0][0][0];
                xitem(pb,           rq,            tid);   // plane 2k
                xitem(pb + TPLANEF, rq + RSPLANEF, tid);   // plane 2k+1
            }
            bar_arrive_n(BAR_FULL0 + q, NTHREADS);  // rs[q] published (pair k)
        }
    } else {
        // ========================= CONSUMER (128) =========================
        const int ctid = tid - NPROD;
        const int ctx  = ctid & 31;
        const int cty  = ctid >> 5;              // 0..3
        const int yb   = 2 * cty;

        float ring[5][2][5];
        float run[2][5];
        #pragma unroll
        for (int s = 0; s < 5; s++)
            #pragma unroll
            for (int pp = 0; pp < 2; pp++)
                #pragma unroll
                for (int c = 0; c < 5; c++) ring[s][pp][c] = 0.f;
        #pragma unroll
        for (int pp = 0; pp < 2; pp++)
            #pragma unroll
            for (int c = 0; c < 5; c++) run[pp][c] = 0.f;

        bar_arrive_n(BAR_EMPTY0, NTHREADS);
        bar_arrive_n(BAR_EMPTY1, NTHREADS);

        // one plane of consumer work; s = ring slot (compile-time)
        auto consume_plane = [&](const float* rp, int s, bool live) {
            #pragma unroll
            for (int c = 0; c < 5; c++) {
                const float* col = rp + c * RSCHF + yb * 32 + ctx;
                float v0 = col[0*32];
                float v1 = col[1*32];
                float v2 = col[2*32];
                float v3 = col[3*32];
                float v4 = col[4*32];
                float v5 = col[5*32];
                float n0 = ((v0 + v1) + (v2 + v3)) + v4;
                float n1 = n0 - v0 + v5;
                run[0][c]    += n0 - ring[s][0][c];
                ring[s][0][c] = n0;
                run[1][c]    += n1 - ring[s][1][c];
                ring[s][1][c] = n1;
            }
            if (live) {
                const float inv = 1.f / 125.f;
                #pragma unroll
                for (int pp = 0; pp < 2; pp++) {
                    float sm = run[pp][0] * inv;
                    float tm = run[pp][1] * inv;
                    float sv = fmaf(-sm, sm, run[pp][2] * inv);
                    float tv = fmaf(-tm, tm, run[pp][3] * inv);
                    float cr = fmaf(-sm, tm, run[pp][4] * inv);
                    float den = fmaf(sv, tv, 1e-5f);
                    acc += __fdividef(cr * cr, den);
                }
            }
        };

        for (int kb = 0; kb < 45; kb += 5) {
            #pragma unroll
            for (int jj = 0; jj < 5; jj++) {     // compile-time slot pattern
                const int k = kb + jj;
                if (k >= NPAIRS) break;          // 42 = 8*5 + 2
                const int q  = k & 1;
                const int s0 = (2 * jj) % 5;
                const int s1 = (2 * jj + 1) % 5;
                bar_sync_n(BAR_FULL0 + q, NTHREADS);

                const float* rq = &rs[q][0][0][0][0];
                consume_plane(rq,            s0, k >= 2);  // plane 2k
                consume_plane(rq + RSPLANEF, s1, k >= 2);  // plane 2k+1

                bar_arrive_n(BAR_EMPTY0 + q, NTHREADS);
            }
        }
    }

    // ---- block reduction over all 256 threads (producers contribute 0) ----
    __syncthreads();
    #pragma unroll
    for (int o = 16; o > 0; o >>= 1)
        acc += __shfl_xor_sync(0xffffffffu, acc, o);
    if ((tid & 31) == 0) wsum[tid >> 5] = acc;
    __syncthreads();

    if (tid == 0) {
        float bsum = 0.f;
        #pragma unroll
        for (int i = 0; i < 8; i++) bsum += wsum[i];
        atomicAdd(&g_acc, (double)bsum);
        __threadfence();
        unsigned done = atomicAdd(&g_cnt, 1u);
        if (done == NBLOCKS - 1) {
            double total = atomicAdd(&g_acc, 0.0);  // fenced read
            const double n = 2.0 * 160.0 * 192.0 * 192.0;
            float loss = (float)(1.0 - total / n);
            if (isnan(loss) || isinf(loss)) loss = 1.0f;
            out[0] = loss;
            *((volatile double*)&g_acc)   = 0.0;
            *((volatile unsigned*)&g_cnt) = 0u;
        }
    }
}

extern "C" void kernel_launch(void* const* d_in, const int* in_sizes, int n_in,
                              void* d_out, int out_size)
{
    (void)in_sizes; (void)n_in; (void)out_size;
    const float* src = (const float*)d_in[0];
    const float* tgt = (const float*)d_in[1];

    lncc_k<<<dim3(6, 24, 4), NTHREADS>>>(src, tgt, (float*)d_out);
}

// round 9
// speedup vs baseline: 1.4565x; 1.1071x over previous
#include <cuda_runtime.h>
#include <cuda_fp16.h>
#include <math.h>
#include <stdint.h>

#define W_ 192
#define H_ 192
#define D_ 160
#define HW_ (H_ * W_)
#define CHUNK 80
#define NPAIRS  42
#define NBLOCKS (6 * 24 * 4)

#define NTHREADS 256
#define NPROD    128

#define BAR_FULL0  1
#define BAR_FULL1  2
#define BAR_EMPTY0 3
#define BAR_EMPTY1 4
#define BAR_PROD   5

// tile geometry: 32 x 8 outputs, halo 36 x 12
#define HROWS 12
#define TROWF 480              /* floats per img plane: 12*40 */
#define TPLANEF 960            /* floats per plane (2 imgs) */
#define TPAIRF 1920            /* floats per pair buffer */
#define RSCHH 384              /* rs channel stride in HALVES: 12*32 */
#define RSPLANEH 1920          /* rs plane stride in halves: 5*384 */
#define NXITEM 96              /* 12 rows * 8 groups */
#define NPAIRS_LD 432          /* 12*18*2 8B pairs per plane */

__device__ double   g_acc;
__device__ unsigned g_cnt;

static __device__ __forceinline__ void bar_sync_n(int id, int cnt) {
    asm volatile("bar.sync %0, %1;" :: "r"(id), "r"(cnt) : "memory");
}
static __device__ __forceinline__ void bar_arrive_n(int id, int cnt) {
    asm volatile("bar.arrive %0, %1;" :: "r"(id), "r"(cnt) : "memory");
}
static __device__ __forceinline__ void cp_async8(uint32_t dst, const float* src,
                                                 unsigned srcsz) {
    asm volatile("cp.async.ca.shared.global [%0], [%1], 8, %2;"
                 :: "r"(dst), "l"(src), "r"(srcsz) : "memory");
}
static __device__ __forceinline__ void cp_commit() {
    asm volatile("cp.async.commit_group;" ::: "memory");
}
static __device__ __forceinline__ void cp_wait2() {
    asm volatile("cp.async.wait_group 2;" ::: "memory");
}

__global__ void __launch_bounds__(NTHREADS, 2)
lncc_k(const float* __restrict__ src, const float* __restrict__ tgt,
       float* __restrict__ out)
{
    // tile: 3 pair-buffers x 2 planes x [img][haloRow(12)][col(36 pad 40)] fp32
    __shared__ float tile[3][2][2][HROWS][40];
    // rs: 2 buffers x 2 planes x [ch(5)][haloRow(12)][x(32)] fp16
    __shared__ __align__(16) __half rs[2][2][5][HROWS][32];
    __shared__ float wsum[8];

    const int tid = threadIdx.x;
    const int x0  = blockIdx.x * 32;
    const int y0  = blockIdx.y * 8;
    const int b   = blockIdx.z >> 1;
    const int z0  = (blockIdx.z & 1) * CHUNK;
    const int zstart = z0 - 2;

    const float* baseS = src + (size_t)b * (D_ * HW_);
    const float* baseT = tgt + (size_t)b * (D_ * HW_);

    float acc = 0.f;

    if (tid < NPROD) {
        // ========================= PRODUCER (128) =========================
        uint32_t soffb[4];
        const float* gbase[4];
        unsigned vmask = 0;   // bit sl: used AND xy-valid
        unsigned umask = 0;   // bit sl: used
        #pragma unroll
        for (int sl = 0; sl < 4; sl++) {
            soffb[sl] = 0; gbase[sl] = baseS;
            const int i = tid + NPROD * sl;
            if (i < NPAIRS_LD) {
                umask |= 1u << sl;
                const int img = (i >= 216) ? 1 : 0;
                const int j   = i - img * 216;
                const int row = j / 18;
                const int pc  = j - row * 18;
                soffb[sl] = (uint32_t)(img * TROWF + row * 40 + pc * 2) * 4u;
                const int gy = y0 + row - 2;
                const int gx = x0 + pc * 2 - 2;  // even; pairs never straddle W
                const bool v = ((unsigned)gy < (unsigned)H_) &&
                               ((unsigned)gx < (unsigned)W_);
                if (v) vmask |= 1u << sl;
                gbase[sl] = (img ? baseT : baseS) + (v ? (gy * W_ + gx) : 0);
            }
        }

        const uint32_t sbase =
            (uint32_t)__cvta_generic_to_shared(&tile[0][0][0][0][0]);

        auto issue_pair = [&](int m) {          // planes 2m,2m+1 -> pairbuf m%3
            const uint32_t pb = sbase + (uint32_t)(m % 3) * (TPAIRF * 4u);
            #pragma unroll
            for (int pl = 0; pl < 2; pl++) {
                const int zp   = zstart + 2 * m + pl;
                const bool zin = (unsigned)zp < (unsigned)D_;
                const int zoff = zin ? zp * HW_ : 0;
                const uint32_t tb = pb + (uint32_t)pl * (TPLANEF * 4u);
                #pragma unroll
                for (int sl = 0; sl < 4; sl++) {
                    if (umask & (1u << sl)) {
                        unsigned sz = (zin && (vmask & (1u << sl))) ? 8u : 0u;
                        cp_async8(tb + soffb[sl], gbase[sl] + zoff, sz);
                    }
                }
            }
            cp_commit();
        };

        // pack 4 fp32 windows -> uint2 of 4 halves, single 8B store
        auto st_h4 = [](__half* dst, float a, float b2, float c, float d) {
            union { __half2 h[2]; uint2 u; } pk;
            pk.h[0] = __floats2half2_rn(a, b2);
            pk.h[1] = __floats2half2_rn(c, d);
            *(uint2*)dst = pk.u;
        };

        // x-phase for one item (r, x4): tile plane tb -> rs plane rsq (fp16)
        auto xitem = [&](const float* tb, __half* rsq, int item) {
            const int r  = item >> 3;
            const int x4 = (item & 7) << 2;
            const float* rowS = tb + r * 40 + x4;
            const float* rowT = rowS + TROWF;
            float4 a0 = *(const float4*)(rowS);
            float4 a1 = *(const float4*)(rowS + 4);
            float4 b0 = *(const float4*)(rowT);
            float4 b1 = *(const float4*)(rowT + 4);
            float sc[8] = {a0.x,a0.y,a0.z,a0.w,a1.x,a1.y,a1.z,a1.w};
            float tc[8] = {b0.x,b0.y,b0.z,b0.w,b1.x,b1.y,b1.z,b1.w};
            const int ro = r * 32 + x4;
            {
                float S0=0.f, T0=0.f;
                #pragma unroll
                for (int j = 0; j < 5; j++) { S0 += sc[j]; T0 += tc[j]; }
                float Sv[4], Tv[4];
                Sv[0]=S0; Tv[0]=T0;
                #pragma unroll
                for (int w = 1; w < 4; w++) {
                    Sv[w] = Sv[w-1] - sc[w-1] + sc[w+4];
                    Tv[w] = Tv[w-1] - tc[w-1] + tc[w+4];
                }
                st_h4(rsq + 0*RSCHH + ro, Sv[0],Sv[1],Sv[2],Sv[3]);
                st_h4(rsq + 1*RSCHH + ro, Tv[0],Tv[1],Tv[2],Tv[3]);
            }
            {
                float SS0=0.f, TT0=0.f;
                #pragma unroll
                for (int j = 0; j < 5; j++) {
                    SS0 = fmaf(sc[j], sc[j], SS0);
                    TT0 = fmaf(tc[j], tc[j], TT0);
                }
                float SSv[4], TTv[4];
                SSv[0]=SS0; TTv[0]=TT0;
                #pragma unroll
                for (int w = 1; w < 4; w++) {
                    SSv[w] = SSv[w-1] - sc[w-1]*sc[w-1] + sc[w+4]*sc[w+4];
                    TTv[w] = TTv[w-1] - tc[w-1]*tc[w-1] + tc[w+4]*tc[w+4];
                }
                st_h4(rsq + 2*RSCHH + ro, SSv[0],SSv[1],SSv[2],SSv[3]);
                st_h4(rsq + 3*RSCHH + ro, TTv[0],TTv[1],TTv[2],TTv[3]);
            }
            {
                float ST0=0.f;
                #pragma unroll
                for (int j = 0; j < 5; j++) ST0 = fmaf(sc[j], tc[j], ST0);
                float STv[4];
                STv[0]=ST0;
                #pragma unroll
                for (int w = 1; w < 4; w++)
                    STv[w] = STv[w-1] - sc[w-1]*tc[w-1] + sc[w+4]*tc[w+4];
                st_h4(rsq + 4*RSCHH + ro, STv[0],STv[1],STv[2],STv[3]);
            }
        };

        issue_pair(0);
        issue_pair(1);

        for (int k = 0; k < NPAIRS; k++) {
            const int q = k & 1;
            bar_sync_n(BAR_EMPTY0 + q, NTHREADS);
            issue_pair(k + 2);
            cp_wait2();                          // pair k's group has landed
            bar_sync_n(BAR_PROD, NPROD);         // cross-thread visibility

            if (tid < NXITEM) {
                const float* pb = &tile[k % 3][0][0][0][0];
                __half* rq = &rs[q][0][0][0][0];
                xitem(pb,           rq,            tid);   // plane 2k
                xitem(pb + TPLANEF, rq + RSPLANEH, tid);   // plane 2k+1
            }
            bar_arrive_n(BAR_FULL0 + q, NTHREADS);  // rs[q] published (pair k)
        }
    } else {
        // ========================= CONSUMER (128) =========================
        // thread owns an x-pair (2*ctx2, 2*ctx2+1) at row cty
        const int ctid = tid - NPROD;
        const int ctx2 = ctid & 15;              // 0..15 -> x pair
        const int cty  = ctid >> 4;              // 0..7

        float ring[5][2][5];
        float run[2][5];
        #pragma unroll
        for (int s = 0; s < 5; s++)
            #pragma unroll
            for (int pp = 0; pp < 2; pp++)
                #pragma unroll
                for (int c = 0; c < 5; c++) ring[s][pp][c] = 0.f;
        #pragma unroll
        for (int pp = 0; pp < 2; pp++)
            #pragma unroll
            for (int c = 0; c < 5; c++) run[pp][c] = 0.f;

        bar_arrive_n(BAR_EMPTY0, NTHREADS);
        bar_arrive_n(BAR_EMPTY1, NTHREADS);

        const int cbase = cty * 16 + ctx2;       // half2 offset of (row cty, xpair)

        // one plane of consumer work; s = ring slot (compile-time)
        auto consume_plane = [&](const __half* rp, int s, bool live) {
            #pragma unroll
            for (int c = 0; c < 5; c++) {
                const __half2* col = (const __half2*)(rp + c * RSCHH) + cbase;
                __half2 a0 = col[0*16];
                __half2 a1 = col[1*16];
                __half2 a2 = col[2*16];
                __half2 a3 = col[3*16];
                __half2 a4 = col[4*16];
                __half2 sh = __hadd2(__hadd2(__hadd2(a0, a1), __hadd2(a2, a3)), a4);
                float2 n = __half22float2(sh);
                run[0][c]    += n.x - ring[s][0][c];
                ring[s][0][c] = n.x;
                run[1][c]    += n.y - ring[s][1][c];
                ring[s][1][c] = n.y;
            }
            if (live) {
                const float inv = 1.f / 125.f;
                #pragma unroll
                for (int pp = 0; pp < 2; pp++) {
                    float sm = run[pp][0] * inv;
                    float tm = run[pp][1] * inv;
                    float sv = fmaf(-sm, sm, run[pp][2] * inv);
                    float tv = fmaf(-tm, tm, run[pp][3] * inv);
                    float cr = fmaf(-sm, tm, run[pp][4] * inv);
                    float den = fmaf(sv, tv, 1e-5f);
                    acc += __fdividef(cr * cr, den);
                }
            }
        };

        for (int kb = 0; kb < 45; kb += 5) {
            #pragma unroll
            for (int jj = 0; jj < 5; jj++) {     // compile-time slot pattern
                const int k = kb + jj;
                if (k >= NPAIRS) break;          // 42 = 8*5 + 2
                const int q  = k & 1;
                const int s0 = (2 * jj) % 5;
                const int s1 = (2 * jj + 1) % 5;
                bar_sync_n(BAR_FULL0 + q, NTHREADS);

                const __half* rq = &rs[q][0][0][0][0];
                consume_plane(rq,            s0, k >= 2);  // plane 2k
                consume_plane(rq + RSPLANEH, s1, k >= 2);  // plane 2k+1

                bar_arrive_n(BAR_EMPTY0 + q, NTHREADS);
            }
        }
    }

    // ---- block reduction over all 256 threads (producers contribute 0) ----
    __syncthreads();
    #pragma unroll
    for (int o = 16; o > 0; o >>= 1)
        acc += __shfl_xor_sync(0xffffffffu, acc, o);
    if ((tid & 31) == 0) wsum[tid >> 5] = acc;
    __syncthreads();

    if (tid == 0) {
        float bsum = 0.f;
        #pragma unroll
        for (int i = 0; i < 8; i++) bsum += wsum[i];
        atomicAdd(&g_acc, (double)bsum);
        __threadfence();
        unsigned done = atomicAdd(&g_cnt, 1u);
        if (done == NBLOCKS - 1) {
            double total = atomicAdd(&g_acc, 0.0);  // fenced read
            const double n = 2.0 * 160.0 * 192.0 * 192.0;
            float loss = (float)(1.0 - total / n);
            if (isnan(loss) || isinf(loss)) loss = 1.0f;
            out[0] = loss;
            *((volatile double*)&g_acc)   = 0.0;
            *((volatile unsigned*)&g_cnt) = 0u;
        }
    }
}

extern "C" void kernel_launch(void* const* d_in, const int* in_sizes, int n_in,
                              void* d_out, int out_size)
{
    (void)in_sizes; (void)n_in; (void)out_size;
    const float* src = (const float*)d_in[0];
    const float* tgt = (const float*)d_in[1];

    lncc_k<<<dim3(6, 24, 4), NTHREADS>>>(src, tgt, (float*)d_out);
}